// round 1
// baseline (speedup 1.0000x reference)
#include <cuda_runtime.h>
#include <cuda_bf16.h>
#include <math.h>
#include <float.h>

// Problem constants
#define Bsz 4
#define Sq  2048
#define Dm  1024
#define Hn  16
#define HD  64
#define MROWS (Bsz * Sq)          // 8192
#define ATT_SCALE 0.125f          // 64^-0.5

// Scratch (device globals — no allocation allowed)
__device__ float g_Q[MROWS * Dm];
__device__ float g_K[MROWS * Dm];
__device__ float g_V[MROWS * Dm];
__device__ float g_AO[MROWS * Dm];

// ---------------------------------------------------------------------------
// SGEMM + bias: C[M,N] = A[M,K] @ W[K,N] + bias[N]
// BM=128, BN=128, BK=16, 256 threads, 8x8 per thread
// ---------------------------------------------------------------------------
#define BM 128
#define BN 128
#define BK 16

__global__ __launch_bounds__(256, 2)
void sgemm_bias(const float* __restrict__ A, const float* __restrict__ W,
                const float* __restrict__ bias, float* __restrict__ C,
                int M, int N, int K)
{
    __shared__ float As[BK][BM];   // transposed A tile
    __shared__ float Bs[BK][BN];

    const int tid = threadIdx.x;
    const int tx  = tid & 15;       // 0..15
    const int ty  = tid >> 4;       // 0..15
    const int bm  = blockIdx.y * BM;
    const int bn  = blockIdx.x * BN;

    float acc[8][8];
    #pragma unroll
    for (int i = 0; i < 8; i++)
        #pragma unroll
        for (int j = 0; j < 8; j++)
            acc[i][j] = 0.0f;

    const float* Ap = A + (size_t)bm * K;

    for (int k0 = 0; k0 < K; k0 += BK) {
        // Load A tile (BM x BK) transposed into As[k][m]
        #pragma unroll
        for (int i = 0; i < 2; i++) {
            int f   = tid + i * 256;          // float4 index 0..511
            int row = f >> 2;                 // 0..127
            int kc  = (f & 3) << 2;           // 0,4,8,12
            float4 v = *(const float4*)(Ap + (size_t)row * K + k0 + kc);
            As[kc + 0][row] = v.x;
            As[kc + 1][row] = v.y;
            As[kc + 2][row] = v.z;
            As[kc + 3][row] = v.w;
        }
        // Load B tile (BK x BN) direct
        #pragma unroll
        for (int i = 0; i < 2; i++) {
            int f  = tid + i * 256;
            int kr = f >> 5;                  // 0..15
            int nc = (f & 31) << 2;           // 0..124
            float4 v = *(const float4*)(W + (size_t)(k0 + kr) * N + bn + nc);
            *(float4*)&Bs[kr][nc] = v;
        }
        __syncthreads();

        #pragma unroll
        for (int k = 0; k < BK; k++) {
            float a[8], b[8];
            *(float4*)(a)     = *(const float4*)&As[k][ty * 4];
            *(float4*)(a + 4) = *(const float4*)&As[k][64 + ty * 4];
            *(float4*)(b)     = *(const float4*)&Bs[k][tx * 4];
            *(float4*)(b + 4) = *(const float4*)&Bs[k][64 + tx * 4];
            #pragma unroll
            for (int i = 0; i < 8; i++)
                #pragma unroll
                for (int j = 0; j < 8; j++)
                    acc[i][j] = fmaf(a[i], b[j], acc[i][j]);
        }
        __syncthreads();
    }

    // Epilogue: add bias, store
    #pragma unroll
    for (int i = 0; i < 8; i++) {
        int lr = (i < 4) ? (ty * 4 + i) : (64 + ty * 4 + i - 4);
        int r  = bm + lr;
        #pragma unroll
        for (int jj = 0; jj < 2; jj++) {
            int c = bn + ((jj == 0) ? (tx * 4) : (64 + tx * 4));
            float4 o;
            o.x = acc[i][jj * 4 + 0] + bias[c + 0];
            o.y = acc[i][jj * 4 + 1] + bias[c + 1];
            o.z = acc[i][jj * 4 + 2] + bias[c + 2];
            o.w = acc[i][jj * 4 + 3] + bias[c + 3];
            *(float4*)(C + (size_t)r * N + c) = o;
        }
    }
}

// ---------------------------------------------------------------------------
// Flash attention fp32.
// Q/K/V in [B, S, H, HD] layout, i.e. element (b,h,s,d) at ((b*S+s)*D + h*HD + d).
// One block per (b*H + h, query tile of 64). 256 threads; thread (ty,tx)
// owns 4 query rows (4*ty..) and 4 cols (4*tx..) of each 64x64 tile.
// smem: Qts[k][r], KP (Kts[k][c] aliased with Pts[key][r]), Vs[key][d] = 48KB.
// ---------------------------------------------------------------------------
__global__ __launch_bounds__(256, 1)
void attn_flash(const float* __restrict__ Qg, const float* __restrict__ Kg,
                const float* __restrict__ Vg, float* __restrict__ Og)
{
    __shared__ float Qts[64][64];  // [dim][q-row]
    __shared__ float KP [64][64];  // Kts: [dim][key]   then  Pts: [key][q-row]
    __shared__ float Vs [64][64];  // [key][dim]

    const int tid = threadIdx.x;
    const int tx  = tid & 15;
    const int ty  = tid >> 4;

    const int bh = blockIdx.y;         // 0..63
    const int b  = bh / Hn;
    const int h  = bh % Hn;
    const int q0 = blockIdx.x * 64;

    const size_t headoff = (size_t)(b * Sq) * Dm + h * HD;

    // Load Q tile transposed: thread covers row tid/4, dims (tid%4)*16..+15
    {
        int r  = tid >> 2;
        int c0 = (tid & 3) << 4;
        const float* src = Qg + headoff + (size_t)(q0 + r) * Dm + c0;
        #pragma unroll
        for (int u = 0; u < 4; u++) {
            float4 v = *(const float4*)(src + u * 4);
            Qts[c0 + u * 4 + 0][r] = v.x;
            Qts[c0 + u * 4 + 1][r] = v.y;
            Qts[c0 + u * 4 + 2][r] = v.z;
            Qts[c0 + u * 4 + 3][r] = v.w;
        }
    }

    float o[4][4];
    float m[4], l[4];
    #pragma unroll
    for (int i = 0; i < 4; i++) {
        m[i] = -FLT_MAX; l[i] = 0.0f;
        #pragma unroll
        for (int j = 0; j < 4; j++) o[i][j] = 0.0f;
    }

    for (int t = 0; t < Sq / 64; t++) {
        const int k0 = t * 64;
        __syncthreads();   // prev iteration finished reading KP/Vs

        // Load K tile transposed + V tile direct
        {
            int r  = tid >> 2;
            int c0 = (tid & 3) << 4;
            const float* ksrc = Kg + headoff + (size_t)(k0 + r) * Dm + c0;
            const float* vsrc = Vg + headoff + (size_t)(k0 + r) * Dm + c0;
            #pragma unroll
            for (int u = 0; u < 4; u++) {
                float4 v = *(const float4*)(ksrc + u * 4);
                KP[c0 + u * 4 + 0][r] = v.x;
                KP[c0 + u * 4 + 1][r] = v.y;
                KP[c0 + u * 4 + 2][r] = v.z;
                KP[c0 + u * 4 + 3][r] = v.w;
                *(float4*)&Vs[r][c0 + u * 4] = *(const float4*)(vsrc + u * 4);
            }
        }
        __syncthreads();

        // s = Q @ K^T (64-dim reduction)
        float s[4][4];
        #pragma unroll
        for (int i = 0; i < 4; i++)
            #pragma unroll
            for (int j = 0; j < 4; j++) s[i][j] = 0.0f;

        #pragma unroll 8
        for (int k = 0; k < 64; k++) {
            float4 qa = *(const float4*)&Qts[k][ty * 4];
            float4 kb = *(const float4*)&KP [k][tx * 4];
            float a[4] = {qa.x, qa.y, qa.z, qa.w};
            float c[4] = {kb.x, kb.y, kb.z, kb.w};
            #pragma unroll
            for (int i = 0; i < 4; i++)
                #pragma unroll
                for (int j = 0; j < 4; j++)
                    s[i][j] = fmaf(a[i], c[j], s[i][j]);
        }

        // Online softmax over each of this thread's 4 rows
        float p[4][4];
        float corr[4], rs[4];
        #pragma unroll
        for (int i = 0; i < 4; i++) {
            float tm = -FLT_MAX;
            #pragma unroll
            for (int j = 0; j < 4; j++) {
                s[i][j] *= ATT_SCALE;
                tm = fmaxf(tm, s[i][j]);
            }
            // max across the 16 lanes holding this row
            #pragma unroll
            for (int w = 8; w >= 1; w >>= 1)
                tm = fmaxf(tm, __shfl_xor_sync(0xffffffffu, tm, w));
            float nm = fmaxf(m[i], tm);
            float r = 0.0f;
            #pragma unroll
            for (int j = 0; j < 4; j++) {
                p[i][j] = expf(s[i][j] - nm);
                r += p[i][j];
            }
            #pragma unroll
            for (int w = 8; w >= 1; w >>= 1)
                r += __shfl_xor_sync(0xffffffffu, r, w);
            corr[i] = expf(m[i] - nm);
            rs[i] = r;
            m[i] = nm;
        }
        #pragma unroll
        for (int i = 0; i < 4; i++) {
            l[i] = l[i] * corr[i] + rs[i];
            #pragma unroll
            for (int j = 0; j < 4; j++) o[i][j] *= corr[i];
        }

        __syncthreads();   // everyone done reading Kts before overwriting with P

        // Store P transposed into KP as Pts[key][q-row]
        #pragma unroll
        for (int i = 0; i < 4; i++)
            #pragma unroll
            for (int j = 0; j < 4; j++)
                KP[tx * 4 + j][ty * 4 + i] = p[i][j];
        __syncthreads();

        // o += P @ V  (64-key reduction)
        #pragma unroll 8
        for (int k = 0; k < 64; k++) {
            float4 pa = *(const float4*)&KP[k][ty * 4];
            float4 vb = *(const float4*)&Vs[k][tx * 4];
            float a[4] = {pa.x, pa.y, pa.z, pa.w};
            float c[4] = {vb.x, vb.y, vb.z, vb.w};
            #pragma unroll
            for (int i = 0; i < 4; i++)
                #pragma unroll
                for (int j = 0; j < 4; j++)
                    o[i][j] = fmaf(a[i], c[j], o[i][j]);
        }
    }

    // Normalize + store to [B,S,H,HD] layout
    #pragma unroll
    for (int i = 0; i < 4; i++) {
        float inv = 1.0f / l[i];
        int r = q0 + ty * 4 + i;
        float4 out;
        out.x = o[i][0] * inv;
        out.y = o[i][1] * inv;
        out.z = o[i][2] * inv;
        out.w = o[i][3] * inv;
        *(float4*)(Og + headoff + (size_t)r * Dm + tx * 4) = out;
    }
}

// ---------------------------------------------------------------------------
extern "C" void kernel_launch(void* const* d_in, const int* in_sizes, int n_in,
                              void* d_out, int out_size)
{
    const float* x  = (const float*)d_in[0];
    const float* wq = (const float*)d_in[1];
    const float* bq = (const float*)d_in[2];
    const float* wk = (const float*)d_in[3];
    const float* bk = (const float*)d_in[4];
    const float* wv = (const float*)d_in[5];
    const float* bv = (const float*)d_in[6];
    const float* wo = (const float*)d_in[7];
    const float* bo = (const float*)d_in[8];
    float* out = (float*)d_out;

    float *qp, *kp, *vp, *aop;
    cudaGetSymbolAddress((void**)&qp,  g_Q);
    cudaGetSymbolAddress((void**)&kp,  g_K);
    cudaGetSymbolAddress((void**)&vp,  g_V);
    cudaGetSymbolAddress((void**)&aop, g_AO);

    dim3 gg(Dm / BN, MROWS / BM);   // (8, 64)
    sgemm_bias<<<gg, 256>>>(x, wq, bq, qp, MROWS, Dm, Dm);
    sgemm_bias<<<gg, 256>>>(x, wk, bk, kp, MROWS, Dm, Dm);
    sgemm_bias<<<gg, 256>>>(x, wv, bv, vp, MROWS, Dm, Dm);

    dim3 ga(Sq / 64, Bsz * Hn);     // (32, 64)
    attn_flash<<<ga, 256>>>(qp, kp, vp, aop);

    sgemm_bias<<<gg, 256>>>(aop, wo, bo, out, MROWS, Dm, Dm);
}

// round 2
// speedup vs baseline: 2.1146x; 2.1146x over previous
#include <cuda_runtime.h>
#include <cuda_bf16.h>
#include <math.h>
#include <float.h>

// Problem constants
#define Bsz 4
#define Sq  2048
#define Dm  1024
#define Hn  16
#define HD  64
#define MROWS (Bsz * Sq)          // 8192
#define ATT_SCALE 0.125f          // 64^-0.5

typedef unsigned long long ull;

// ---- packed f32x2 helpers (FFMA2 path: ptxas never auto-generates) ----
__device__ __forceinline__ ull splat2(float x) {
    ull r; unsigned u = __float_as_uint(x);
    asm("mov.b64 %0, {%1, %1};" : "=l"(r) : "r"(u));
    return r;
}
__device__ __forceinline__ ull pack2(float lo, float hi) {
    ull r;
    asm("mov.b64 %0, {%1, %2};" : "=l"(r)
        : "r"(__float_as_uint(lo)), "r"(__float_as_uint(hi)));
    return r;
}
__device__ __forceinline__ void unpack2(ull v, float &lo, float &hi) {
    unsigned a, b;
    asm("mov.b64 {%0, %1}, %2;" : "=r"(a), "=r"(b) : "l"(v));
    lo = __uint_as_float(a); hi = __uint_as_float(b);
}
__device__ __forceinline__ void ffma2(ull &d, ull a, ull b) {
    asm("fma.rn.f32x2 %0, %1, %2, %0;" : "+l"(d) : "l"(a), "l"(b));
}
__device__ __forceinline__ void fmul2(ull &d, ull a) {
    asm("mul.rn.f32x2 %0, %0, %1;" : "+l"(d) : "l"(a));
}

// Scratch (device globals — no allocation allowed)
__device__ float g_Q[MROWS * Dm];
__device__ float g_K[MROWS * Dm];
__device__ float g_V[MROWS * Dm];
__device__ float g_AO[MROWS * Dm];

// ---------------------------------------------------------------------------
// SGEMM + bias with FFMA2: C[M,N] = A[M,K] @ W[K,N] + bias[N]
// BM=128, BN=128, BK=16, 256 threads, 8x8 per thread (cols split 64/64)
// ---------------------------------------------------------------------------
#define BM 128
#define BN 128
#define BK 16

__global__ __launch_bounds__(256, 2)
void sgemm_bias(const float* __restrict__ A, const float* __restrict__ W,
                const float* __restrict__ bias, float* __restrict__ C,
                int M, int N, int K)
{
    __shared__ float As[BK][BM];   // transposed A tile
    __shared__ float Bs[BK][BN];

    const int tid = threadIdx.x;
    const int tx  = tid & 15;       // 0..15
    const int ty  = tid >> 4;       // 0..15
    const int bm  = blockIdx.y * BM;
    const int bn  = blockIdx.x * BN;

    ull acc2[8][4];
    #pragma unroll
    for (int i = 0; i < 8; i++)
        #pragma unroll
        for (int j = 0; j < 4; j++)
            acc2[i][j] = 0ull;

    const float* Ap = A + (size_t)bm * K;

    for (int k0 = 0; k0 < K; k0 += BK) {
        // Load A tile (BM x BK) transposed into As[k][m]
        #pragma unroll
        for (int i = 0; i < 2; i++) {
            int f   = tid + i * 256;          // float4 index 0..511
            int row = f >> 2;                 // 0..127
            int kc  = (f & 3) << 2;           // 0,4,8,12
            float4 v = *(const float4*)(Ap + (size_t)row * K + k0 + kc);
            As[kc + 0][row] = v.x;
            As[kc + 1][row] = v.y;
            As[kc + 2][row] = v.z;
            As[kc + 3][row] = v.w;
        }
        // Load B tile (BK x BN) direct
        #pragma unroll
        for (int i = 0; i < 2; i++) {
            int f  = tid + i * 256;
            int kr = f >> 5;                  // 0..15
            int nc = (f & 31) << 2;           // 0..124
            float4 v = *(const float4*)(W + (size_t)(k0 + kr) * N + bn + nc);
            *(float4*)&Bs[kr][nc] = v;
        }
        __syncthreads();

        #pragma unroll
        for (int k = 0; k < BK; k++) {
            float a[8];
            *(float4*)(a)     = *(const float4*)&As[k][ty * 4];
            *(float4*)(a + 4) = *(const float4*)&As[k][64 + ty * 4];
            float4 bl = *(const float4*)&Bs[k][tx * 4];
            float4 bh = *(const float4*)&Bs[k][64 + tx * 4];
            ull bp[4];
            bp[0] = pack2(bl.x, bl.y);
            bp[1] = pack2(bl.z, bl.w);
            bp[2] = pack2(bh.x, bh.y);
            bp[3] = pack2(bh.z, bh.w);
            #pragma unroll
            for (int i = 0; i < 8; i++) {
                ull ai = splat2(a[i]);
                ffma2(acc2[i][0], ai, bp[0]);
                ffma2(acc2[i][1], ai, bp[1]);
                ffma2(acc2[i][2], ai, bp[2]);
                ffma2(acc2[i][3], ai, bp[3]);
            }
        }
        __syncthreads();
    }

    // Epilogue: add bias, store (cols tx*4.. and 64+tx*4..)
    #pragma unroll
    for (int i = 0; i < 8; i++) {
        int lr = (i < 4) ? (ty * 4 + i) : (64 + ty * 4 + i - 4);
        int r  = bm + lr;
        #pragma unroll
        for (int jj = 0; jj < 2; jj++) {
            int c = bn + ((jj == 0) ? (tx * 4) : (64 + tx * 4));
            float e0, e1, e2, e3;
            unpack2(acc2[i][jj * 2 + 0], e0, e1);
            unpack2(acc2[i][jj * 2 + 1], e2, e3);
            float4 o;
            o.x = e0 + bias[c + 0];
            o.y = e1 + bias[c + 1];
            o.z = e2 + bias[c + 2];
            o.w = e3 + bias[c + 3];
            *(float4*)(C + (size_t)r * N + c) = o;
        }
    }
}

// ---------------------------------------------------------------------------
// Flash attention fp32 with FFMA2.
// Br=Bc=128, 256 threads, 8x8 micro-tile (rows/cols each split lo64/hi64).
// Dynamic smem 160KB: Qts[64][128], Kts[64][128], Vs[128][64], Pts[128][128].
// Pts uses XOR swizzle: word(key,qrow) = key*128 + ((qrow>>2 ^ ((key>>2)&7))<<2) + (qrow&3)
// ---------------------------------------------------------------------------
#define ATT_BR 128
#define ATT_BC 128
#define ATT_SMEM (160 * 1024)

__global__ __launch_bounds__(256, 1)
void attn_flash2(const float* __restrict__ Qg, const float* __restrict__ Kg,
                 const float* __restrict__ Vg, float* __restrict__ Og)
{
    extern __shared__ float sm[];
    float* Qts = sm;                        // [64][128]  (dim, qrow)
    float* Kts = sm + 64 * 128;             // [64][128]  (dim, key)
    float* Vs  = sm + 2 * 64 * 128;         // [128][64]  (key, dim)
    float* Pts = sm + 2 * 64 * 128 + 128 * 64; // [128][128] swizzled

    const int tid  = threadIdx.x;
    const int tcol = tid & 15;
    const int trow = tid >> 4;

    const int bh = blockIdx.y;
    const int b  = bh >> 4;
    const int h  = bh & 15;
    const int q0 = blockIdx.x * ATT_BR;
    const size_t headoff = (size_t)(b * Sq) * Dm + h * HD;

    // Load Q tile transposed: Qts[dim][qrow]
    {
        int r  = tid >> 1;                 // 0..127
        int c0 = (tid & 1) * 32;           // 0 or 32
        const float* src = Qg + headoff + (size_t)(q0 + r) * Dm + c0;
        #pragma unroll
        for (int u = 0; u < 8; u++) {
            float4 v = *(const float4*)(src + u * 4);
            Qts[(c0 + u * 4 + 0) * 128 + r] = v.x;
            Qts[(c0 + u * 4 + 1) * 128 + r] = v.y;
            Qts[(c0 + u * 4 + 2) * 128 + r] = v.z;
            Qts[(c0 + u * 4 + 3) * 128 + r] = v.w;
        }
    }

    ull o2[4][4];
    float m[8], l[8];
    #pragma unroll
    for (int i = 0; i < 4; i++)
        #pragma unroll
        for (int j = 0; j < 4; j++) o2[i][j] = 0ull;
    #pragma unroll
    for (int i = 0; i < 8; i++) { m[i] = -FLT_MAX; l[i] = 0.0f; }

    for (int t = 0; t < Sq / ATT_BC; t++) {
        __syncthreads();   // prev PV done reading Pts/Vs; QK done with Kts

        // Load K tile transposed + V tile direct
        {
            int r  = tid >> 1;
            int c0 = (tid & 1) * 32;
            const float* ksrc = Kg + headoff + (size_t)(t * ATT_BC + r) * Dm + c0;
            const float* vsrc = Vg + headoff + (size_t)(t * ATT_BC + r) * Dm + c0;
            #pragma unroll
            for (int u = 0; u < 8; u++) {
                float4 kv = *(const float4*)(ksrc + u * 4);
                Kts[(c0 + u * 4 + 0) * 128 + r] = kv.x;
                Kts[(c0 + u * 4 + 1) * 128 + r] = kv.y;
                Kts[(c0 + u * 4 + 2) * 128 + r] = kv.z;
                Kts[(c0 + u * 4 + 3) * 128 + r] = kv.w;
                *(float4*)&Vs[r * 64 + c0 + u * 4] = *(const float4*)(vsrc + u * 4);
            }
        }
        __syncthreads();

        // ---- S = Q @ K^T  (64-dim reduction), packed over columns ----
        ull s2[8][4];
        #pragma unroll
        for (int i = 0; i < 8; i++)
            #pragma unroll
            for (int j = 0; j < 4; j++) s2[i][j] = 0ull;

        #pragma unroll 8
        for (int k = 0; k < 64; k++) {
            const float* qr = &Qts[k * 128];
            const float* kr = &Kts[k * 128];
            float a[8];
            *(float4*)(a)     = *(const float4*)(qr + trow * 4);
            *(float4*)(a + 4) = *(const float4*)(qr + 64 + trow * 4);
            float4 bl = *(const float4*)(kr + tcol * 4);
            float4 bh4 = *(const float4*)(kr + 64 + tcol * 4);
            ull bp[4];
            bp[0] = pack2(bl.x, bl.y);
            bp[1] = pack2(bl.z, bl.w);
            bp[2] = pack2(bh4.x, bh4.y);
            bp[3] = pack2(bh4.z, bh4.w);
            #pragma unroll
            for (int i = 0; i < 8; i++) {
                ull ai = splat2(a[i]);
                ffma2(s2[i][0], ai, bp[0]);
                ffma2(s2[i][1], ai, bp[1]);
                ffma2(s2[i][2], ai, bp[2]);
                ffma2(s2[i][3], ai, bp[3]);
            }
        }

        // ---- online softmax, two 4-row half-passes; store P swizzled ----
        float corr[8];
        #pragma unroll
        for (int half = 0; half < 2; half++) {
            float pp[4][8];
            #pragma unroll
            for (int i = 0; i < 4; i++) {
                int r = half * 4 + i;
                float v[8];
                unpack2(s2[r][0], v[0], v[1]);
                unpack2(s2[r][1], v[2], v[3]);
                unpack2(s2[r][2], v[4], v[5]);
                unpack2(s2[r][3], v[6], v[7]);
                float tm = -FLT_MAX;
                #pragma unroll
                for (int c = 0; c < 8; c++) {
                    v[c] *= ATT_SCALE;
                    tm = fmaxf(tm, v[c]);
                }
                #pragma unroll
                for (int w = 8; w >= 1; w >>= 1)
                    tm = fmaxf(tm, __shfl_xor_sync(0xffffffffu, tm, w));
                float nm = fmaxf(m[r], tm);
                float sum = 0.0f;
                #pragma unroll
                for (int c = 0; c < 8; c++) {
                    float pv = __expf(v[c] - nm);
                    pp[i][c] = pv;
                    sum += pv;
                }
                #pragma unroll
                for (int w = 8; w >= 1; w >>= 1)
                    sum += __shfl_xor_sync(0xffffffffu, sum, w);
                float cr = __expf(m[r] - nm);
                corr[r] = cr;
                l[r] = l[r] * cr + sum;
                m[r] = nm;
            }
            // store this half's 4 rows (qrow quad grp = half*16 + trow)
            int grp = half * 16 + trow;
            #pragma unroll
            for (int c = 0; c < 8; c++) {
                int key = (c < 4) ? (tcol * 4 + c) : (64 + tcol * 4 + (c - 4));
                int gp  = grp ^ ((key >> 2) & 7);
                float4 st = make_float4(pp[0][c], pp[1][c], pp[2][c], pp[3][c]);
                *(float4*)&Pts[key * 128 + gp * 4] = st;
            }
        }

        // rescale o2 by corr (packed per row-pair)
        #pragma unroll
        for (int rp = 0; rp < 4; rp++) {
            ull cp = pack2(corr[2 * rp], corr[2 * rp + 1]);
            #pragma unroll
            for (int d = 0; d < 4; d++) fmul2(o2[rp][d], cp);
        }
        __syncthreads();   // P visible to all

        // ---- O += P @ V  (128-key reduction), packed over row-pairs ----
        #pragma unroll 4
        for (int k = 0; k < ATT_BC; k++) {
            int swk = (k >> 2) & 7;
            const float* prow = &Pts[k * 128];
            float4 plo = *(const float4*)(prow + ((trow ^ swk) << 2));
            float4 phi = *(const float4*)(prow + (((16 + trow) ^ swk) << 2));
            float4 vv4 = *(const float4*)&Vs[k * 64 + tcol * 4];
            ull pr[4];
            pr[0] = pack2(plo.x, plo.y);
            pr[1] = pack2(plo.z, plo.w);
            pr[2] = pack2(phi.x, phi.y);
            pr[3] = pack2(phi.z, phi.w);
            ull vv[4];
            vv[0] = splat2(vv4.x);
            vv[1] = splat2(vv4.y);
            vv[2] = splat2(vv4.z);
            vv[3] = splat2(vv4.w);
            #pragma unroll
            for (int rp = 0; rp < 4; rp++) {
                ffma2(o2[rp][0], pr[rp], vv[0]);
                ffma2(o2[rp][1], pr[rp], vv[1]);
                ffma2(o2[rp][2], pr[rp], vv[2]);
                ffma2(o2[rp][3], pr[rp], vv[3]);
            }
        }
    }

    // Normalize + store
    #pragma unroll
    for (int r = 0; r < 8; r++) {
        float inv = 1.0f / l[r];
        int qrow = (r < 4) ? (trow * 4 + r) : (64 + trow * 4 + (r - 4));
        int rp = r >> 1;
        float e[4][2];
        unpack2(o2[rp][0], e[0][0], e[0][1]);
        unpack2(o2[rp][1], e[1][0], e[1][1]);
        unpack2(o2[rp][2], e[2][0], e[2][1]);
        unpack2(o2[rp][3], e[3][0], e[3][1]);
        int hi = r & 1;
        float4 out;
        out.x = e[0][hi] * inv;
        out.y = e[1][hi] * inv;
        out.z = e[2][hi] * inv;
        out.w = e[3][hi] * inv;
        *(float4*)(Og + headoff + (size_t)(q0 + qrow) * Dm + tcol * 4) = out;
    }
}

// ---------------------------------------------------------------------------
extern "C" void kernel_launch(void* const* d_in, const int* in_sizes, int n_in,
                              void* d_out, int out_size)
{
    const float* x  = (const float*)d_in[0];
    const float* wq = (const float*)d_in[1];
    const float* bq = (const float*)d_in[2];
    const float* wk = (const float*)d_in[3];
    const float* bk = (const float*)d_in[4];
    const float* wv = (const float*)d_in[5];
    const float* bv = (const float*)d_in[6];
    const float* wo = (const float*)d_in[7];
    const float* bo = (const float*)d_in[8];
    float* out = (float*)d_out;

    float *qp, *kp, *vp, *aop;
    cudaGetSymbolAddress((void**)&qp,  g_Q);
    cudaGetSymbolAddress((void**)&kp,  g_K);
    cudaGetSymbolAddress((void**)&vp,  g_V);
    cudaGetSymbolAddress((void**)&aop, g_AO);

    cudaFuncSetAttribute(attn_flash2,
                         cudaFuncAttributeMaxDynamicSharedMemorySize, ATT_SMEM);

    dim3 gg(Dm / BN, MROWS / BM);   // (8, 64)
    sgemm_bias<<<gg, 256>>>(x, wq, bq, qp, MROWS, Dm, Dm);
    sgemm_bias<<<gg, 256>>>(x, wk, bk, kp, MROWS, Dm, Dm);
    sgemm_bias<<<gg, 256>>>(x, wv, bv, vp, MROWS, Dm, Dm);

    dim3 ga(Sq / ATT_BR, Bsz * Hn); // (16, 64)
    attn_flash2<<<ga, 256, ATT_SMEM>>>(qp, kp, vp, aop);

    sgemm_bias<<<gg, 256>>>(aop, wo, bo, out, MROWS, Dm, Dm);
}

// round 4
// speedup vs baseline: 2.8455x; 1.3457x over previous
#include <cuda_runtime.h>
#include <cuda_bf16.h>
#include <math.h>
#include <float.h>
#include <stdint.h>

// Problem constants
#define Bsz 4
#define Sq  2048
#define Dm  1024
#define Hn  16
#define HD  64
#define MROWS (Bsz * Sq)          // 8192
#define ATT_SCALE 0.125f

typedef unsigned long long ull;

// ============================ PTX helpers ==================================
__device__ __forceinline__ uint32_t smem_u32(const void* p) {
    uint32_t a;
    asm("{ .reg .u64 t; cvta.to.shared.u64 t, %1; cvt.u32.u64 %0, t; }"
        : "=r"(a) : "l"(p));
    return a;
}
#define SWZ128(o) ((o) ^ (((o) >> 3) & 0x70))

__device__ __forceinline__ void cpa16(uint32_t saddr, const void* g) {
    asm volatile("cp.async.cg.shared.global [%0], [%1], 16;"
                 :: "r"(saddr), "l"(g) : "memory");
}
#define CP_COMMIT() asm volatile("cp.async.commit_group;" ::: "memory")
#define CP_WAIT1()  asm volatile("cp.async.wait_group 1;" ::: "memory")
#define CP_WAIT0()  asm volatile("cp.async.wait_group 0;" ::: "memory")

__device__ __forceinline__ void ldsm4(uint32_t* r, uint32_t addr) {
    asm volatile("ldmatrix.sync.aligned.m8n8.x4.shared.b16 {%0,%1,%2,%3}, [%4];"
                 : "=r"(r[0]), "=r"(r[1]), "=r"(r[2]), "=r"(r[3]) : "r"(addr));
}
__device__ __forceinline__ void mma_bf16(float* d, const uint32_t* a, const uint32_t* b) {
    asm volatile(
        "mma.sync.aligned.m16n8k16.row.col.f32.bf16.bf16.f32 "
        "{%0,%1,%2,%3}, {%4,%5,%6,%7}, {%8,%9}, {%0,%1,%2,%3};"
        : "+f"(d[0]), "+f"(d[1]), "+f"(d[2]), "+f"(d[3])
        : "r"(a[0]), "r"(a[1]), "r"(a[2]), "r"(a[3]), "r"(b[0]), "r"(b[1]));
}

// ---- packed f32x2 helpers ----
__device__ __forceinline__ ull splat2(float x) {
    ull r; unsigned u = __float_as_uint(x);
    asm("mov.b64 %0, {%1, %1};" : "=l"(r) : "r"(u));
    return r;
}
__device__ __forceinline__ ull pack2(float lo, float hi) {
    ull r;
    asm("mov.b64 %0, {%1, %2};" : "=l"(r)
        : "r"(__float_as_uint(lo)), "r"(__float_as_uint(hi)));
    return r;
}
__device__ __forceinline__ void unpack2(ull v, float &lo, float &hi) {
    unsigned a, b;
    asm("mov.b64 {%0, %1}, %2;" : "=r"(a), "=r"(b) : "l"(v));
    lo = __uint_as_float(a); hi = __uint_as_float(b);
}
__device__ __forceinline__ void ffma2(ull &d, ull a, ull b) {
    asm("fma.rn.f32x2 %0, %1, %2, %0;" : "+l"(d) : "l"(a), "l"(b));
}
__device__ __forceinline__ void fmul2(ull &d, ull a) {
    asm("mul.rn.f32x2 %0, %0, %1;" : "+l"(d) : "l"(a));
}

// ============================ scratch ======================================
__device__ float g_Q[MROWS * Dm];
__device__ float g_K[MROWS * Dm];
__device__ float g_V[MROWS * Dm];
__device__ float g_AO[MROWS * Dm];
__device__ __nv_bfloat16 g_Ahi[MROWS * Dm];
__device__ __nv_bfloat16 g_Alo[MROWS * Dm];
__device__ __nv_bfloat16 g_Wthi[Dm * Dm];
__device__ __nv_bfloat16 g_Wtlo[Dm * Dm];

// =================== split conversion: f32 -> bf16 hi/lo ===================
__device__ __forceinline__ void bsplit(float x, __nv_bfloat16 &h, __nv_bfloat16 &l) {
    h = __float2bfloat16(x);
    l = __float2bfloat16(x - __bfloat162float(h));
}

__global__ __launch_bounds__(256)
void fsplit(const float4* __restrict__ in, uint2* __restrict__ hi,
            uint2* __restrict__ lo, int n4)
{
    int i = blockIdx.x * 256 + threadIdx.x;
    if (i >= n4) return;
    float4 v = in[i];
    __nv_bfloat16 h0, h1, h2, h3, l0, l1, l2, l3;
    bsplit(v.x, h0, l0); bsplit(v.y, h1, l1);
    bsplit(v.z, h2, l2); bsplit(v.w, h3, l3);
    __nv_bfloat162 ph0 = __nv_bfloat162(h0, h1), ph1 = __nv_bfloat162(h2, h3);
    __nv_bfloat162 pl0 = __nv_bfloat162(l0, l1), pl1 = __nv_bfloat162(l2, l3);
    uint2 H, L;
    H.x = *(unsigned*)&ph0; H.y = *(unsigned*)&ph1;
    L.x = *(unsigned*)&pl0; L.y = *(unsigned*)&pl1;
    hi[i] = H; lo[i] = L;
}

// ========== transpose + split: W[K,N] f32 -> Wt[N,K] bf16 hi/lo ============
__global__ __launch_bounds__(256)
void wt_split(const float* __restrict__ W, __nv_bfloat16* __restrict__ Thi,
              __nv_bfloat16* __restrict__ Tlo)
{
    __shared__ float t[32][33];
    int n0 = blockIdx.x * 32, k0 = blockIdx.y * 32;
    int tx = threadIdx.x & 31, ty = threadIdx.x >> 5;   // 32 x 8
    #pragma unroll
    for (int i = 0; i < 4; i++)
        t[ty + 8 * i][tx] = W[(size_t)(k0 + ty + 8 * i) * Dm + n0 + tx];
    __syncthreads();
    #pragma unroll
    for (int i = 0; i < 4; i++) {
        float v = t[tx][ty + 8 * i];     // = W[k0+tx][n0+ty+8i]
        __nv_bfloat16 h, l; bsplit(v, h, l);
        size_t o = (size_t)(n0 + ty + 8 * i) * Dm + k0 + tx;
        Thi[o] = h; Tlo[o] = l;
    }
}

// ================== HMMA bf16-split GEMM + bias ===========================
// C[M,N] = (Ahi+Alo)[M,K] @ (Wthi+Wtlo)[N,K]^T + bias   (3-term split)
// Tile 128x128, BK=64 bf16 (128B SW128 rows), cp.async double-buffered.
// 8 warps: 4m x 2n; warp tile 32m x 64n; mma.m16n8k16 row.col bf16.
#define HBK 64
#define HBUF 65536                 // one buffer: AH|AL|BH|BL, 16KB each
#define HSMEM (2 * HBUF)           // 128KB
#define HCHUNKS (Dm / HBK)         // 16

__global__ __launch_bounds__(256, 1)
void gemm_hmma(const __nv_bfloat16* __restrict__ Ahi, const __nv_bfloat16* __restrict__ Alo,
               const __nv_bfloat16* __restrict__ Bhi, const __nv_bfloat16* __restrict__ Blo,
               const float* __restrict__ bias, float* __restrict__ C)
{
    extern __shared__ __align__(1024) char smem[];
    const uint32_t sb = smem_u32(smem);

    const int tid  = threadIdx.x;
    const int wid  = tid >> 5;
    const int lane = tid & 31;
    const int wm   = wid & 3;         // 0..3  (m)
    const int wn   = wid >> 2;        // 0..1  (n)
    const int bm   = blockIdx.y * 128;
    const int bn   = blockIdx.x * 128;

    // cp.async load mapping: 32 rows x 8 segs per array slice per pass
    const int lrow = tid >> 3;        // 0..31
    const int lseg = tid & 7;         // 0..7

    float acc[2][8][4];
    #pragma unroll
    for (int fm = 0; fm < 2; fm++)
        #pragma unroll
        for (int fn = 0; fn < 8; fn++)
            #pragma unroll
            for (int e = 0; e < 4; e++) acc[fm][fn][e] = 0.0f;

    auto issue = [&](int c) {
        const uint32_t s0 = sb + (uint32_t)(c & 1) * HBUF;
        const size_t gofs = (size_t)c * HBK + lseg * 8;
        #pragma unroll
        for (int i = 0; i < 4; i++) {
            int row = lrow + i * 32;
            uint32_t so = SWZ128((uint32_t)(row * 128 + lseg * 16));
            cpa16(s0 + so,         Ahi + (size_t)(bm + row) * Dm + gofs);
            cpa16(s0 + 16384 + so, Alo + (size_t)(bm + row) * Dm + gofs);
            cpa16(s0 + 32768 + so, Bhi + (size_t)(bn + row) * Dm + gofs);
            cpa16(s0 + 49152 + so, Blo + (size_t)(bn + row) * Dm + gofs);
        }
    };

    // ldmatrix lane addressing (within tile)
    const int a_row = wm * 32 + (lane & 15);                  // + fm*16
    const int a_sel = lane >> 4;                              // seg low bit
    const int b_row = wn * 64 + ((lane >> 4) << 3) + (lane & 7);  // + f2*16
    const int b_sel = (lane >> 3) & 1;

    issue(0);
    CP_COMMIT();

    for (int c = 0; c < HCHUNKS; c++) {
        if (c + 1 < HCHUNKS) { issue(c + 1); CP_COMMIT(); CP_WAIT1(); }
        else { CP_COMMIT(); CP_WAIT0(); }
        __syncthreads();

        const uint32_t s0 = sb + (uint32_t)(c & 1) * HBUF;
        #pragma unroll
        for (int ks = 0; ks < 4; ks++) {
            uint32_t ah[2][4], al[2][4];
            #pragma unroll
            for (int fm = 0; fm < 2; fm++) {
                int row = a_row + fm * 16;
                int seg = 2 * ks + a_sel;
                uint32_t ad = s0 + SWZ128((uint32_t)(row * 128 + seg * 16));
                ldsm4(ah[fm], ad);
                ldsm4(al[fm], ad + 16384);
            }
            uint32_t bh[8][2], bl[8][2];
            #pragma unroll
            for (int f2 = 0; f2 < 4; f2++) {
                int row = b_row + f2 * 16;
                int seg = 2 * ks + b_sel;
                uint32_t bd = s0 + 32768 + SWZ128((uint32_t)(row * 128 + seg * 16));
                uint32_t t[4], u[4];
                ldsm4(t, bd);
                ldsm4(u, bd + 16384);
                bh[2*f2][0] = t[0]; bh[2*f2][1] = t[1];
                bh[2*f2+1][0] = t[2]; bh[2*f2+1][1] = t[3];
                bl[2*f2][0] = u[0]; bl[2*f2][1] = u[1];
                bl[2*f2+1][0] = u[2]; bl[2*f2+1][1] = u[3];
            }
            #pragma unroll
            for (int fm = 0; fm < 2; fm++)
                #pragma unroll
                for (int fn = 0; fn < 8; fn++) {
                    mma_bf16(acc[fm][fn], ah[fm], bh[fn]);
                    mma_bf16(acc[fm][fn], ah[fm], bl[fn]);
                    mma_bf16(acc[fm][fn], al[fm], bh[fn]);
                }
        }
        __syncthreads();
    }

    // Epilogue: bias + store
    const int g  = lane >> 2;
    const int tq = lane & 3;
    #pragma unroll
    for (int fm = 0; fm < 2; fm++) {
        #pragma unroll
        for (int fn = 0; fn < 8; fn++) {
            int r0 = bm + wm * 32 + fm * 16 + g;
            int cc = bn + wn * 64 + fn * 8 + tq * 2;
            float b0 = bias[cc], b1 = bias[cc + 1];
            float2 lo, hi;
            lo.x = acc[fm][fn][0] + b0; lo.y = acc[fm][fn][1] + b1;
            hi.x = acc[fm][fn][2] + b0; hi.y = acc[fm][fn][3] + b1;
            *(float2*)(C + (size_t)r0 * Dm + cc) = lo;
            *(float2*)(C + (size_t)(r0 + 8) * Dm + cc) = hi;
        }
    }
}

// ---------------------------------------------------------------------------
// Flash attention fp32 with FFMA2 (unchanged from R2).
// ---------------------------------------------------------------------------
#define ATT_BR 128
#define ATT_BC 128
#define ATT_SMEM (160 * 1024)

__global__ __launch_bounds__(256, 1)
void attn_flash2(const float* __restrict__ Qg, const float* __restrict__ Kg,
                 const float* __restrict__ Vg, float* __restrict__ Og)
{
    extern __shared__ float sm[];
    float* Qts = sm;
    float* Kts = sm + 64 * 128;
    float* Vs  = sm + 2 * 64 * 128;
    float* Pts = sm + 2 * 64 * 128 + 128 * 64;

    const int tid  = threadIdx.x;
    const int tcol = tid & 15;
    const int trow = tid >> 4;

    const int bh = blockIdx.y;
    const int b  = bh >> 4;
    const int h  = bh & 15;
    const int q0 = blockIdx.x * ATT_BR;
    const size_t headoff = (size_t)(b * Sq) * Dm + h * HD;

    {
        int r  = tid >> 1;
        int c0 = (tid & 1) * 32;
        const float* src = Qg + headoff + (size_t)(q0 + r) * Dm + c0;
        #pragma unroll
        for (int u = 0; u < 8; u++) {
            float4 v = *(const float4*)(src + u * 4);
            Qts[(c0 + u * 4 + 0) * 128 + r] = v.x;
            Qts[(c0 + u * 4 + 1) * 128 + r] = v.y;
            Qts[(c0 + u * 4 + 2) * 128 + r] = v.z;
            Qts[(c0 + u * 4 + 3) * 128 + r] = v.w;
        }
    }

    ull o2[4][4];
    float m[8], l[8];
    #pragma unroll
    for (int i = 0; i < 4; i++)
        #pragma unroll
        for (int j = 0; j < 4; j++) o2[i][j] = 0ull;
    #pragma unroll
    for (int i = 0; i < 8; i++) { m[i] = -FLT_MAX; l[i] = 0.0f; }

    for (int t = 0; t < Sq / ATT_BC; t++) {
        __syncthreads();
        {
            int r  = tid >> 1;
            int c0 = (tid & 1) * 32;
            const float* ksrc = Kg + headoff + (size_t)(t * ATT_BC + r) * Dm + c0;
            const float* vsrc = Vg + headoff + (size_t)(t * ATT_BC + r) * Dm + c0;
            #pragma unroll
            for (int u = 0; u < 8; u++) {
                float4 kv = *(const float4*)(ksrc + u * 4);
                Kts[(c0 + u * 4 + 0) * 128 + r] = kv.x;
                Kts[(c0 + u * 4 + 1) * 128 + r] = kv.y;
                Kts[(c0 + u * 4 + 2) * 128 + r] = kv.z;
                Kts[(c0 + u * 4 + 3) * 128 + r] = kv.w;
                *(float4*)&Vs[r * 64 + c0 + u * 4] = *(const float4*)(vsrc + u * 4);
            }
        }
        __syncthreads();

        ull s2[8][4];
        #pragma unroll
        for (int i = 0; i < 8; i++)
            #pragma unroll
            for (int j = 0; j < 4; j++) s2[i][j] = 0ull;

        #pragma unroll 8
        for (int k = 0; k < 64; k++) {
            const float* qr = &Qts[k * 128];
            const float* kr = &Kts[k * 128];
            float a[8];
            *(float4*)(a)     = *(const float4*)(qr + trow * 4);
            *(float4*)(a + 4) = *(const float4*)(qr + 64 + trow * 4);
            float4 bl  = *(const float4*)(kr + tcol * 4);
            float4 bh4 = *(const float4*)(kr + 64 + tcol * 4);
            ull bp[4];
            bp[0] = pack2(bl.x, bl.y);
            bp[1] = pack2(bl.z, bl.w);
            bp[2] = pack2(bh4.x, bh4.y);
            bp[3] = pack2(bh4.z, bh4.w);
            #pragma unroll
            for (int i = 0; i < 8; i++) {
                ull ai = splat2(a[i]);
                ffma2(s2[i][0], ai, bp[0]);
                ffma2(s2[i][1], ai, bp[1]);
                ffma2(s2[i][2], ai, bp[2]);
                ffma2(s2[i][3], ai, bp[3]);
            }
        }

        float corr[8];
        #pragma unroll
        for (int half = 0; half < 2; half++) {
            float pp[4][8];
            #pragma unroll
            for (int i = 0; i < 4; i++) {
                int r = half * 4 + i;
                float v[8];
                unpack2(s2[r][0], v[0], v[1]);
                unpack2(s2[r][1], v[2], v[3]);
                unpack2(s2[r][2], v[4], v[5]);
                unpack2(s2[r][3], v[6], v[7]);
                float tm = -FLT_MAX;
                #pragma unroll
                for (int cc = 0; cc < 8; cc++) {
                    v[cc] *= ATT_SCALE;
                    tm = fmaxf(tm, v[cc]);
                }
                #pragma unroll
                for (int w = 8; w >= 1; w >>= 1)
                    tm = fmaxf(tm, __shfl_xor_sync(0xffffffffu, tm, w));
                float nm = fmaxf(m[r], tm);
                float sum = 0.0f;
                #pragma unroll
                for (int cc = 0; cc < 8; cc++) {
                    float pv = __expf(v[cc] - nm);
                    pp[i][cc] = pv;
                    sum += pv;
                }
                #pragma unroll
                for (int w = 8; w >= 1; w >>= 1)
                    sum += __shfl_xor_sync(0xffffffffu, sum, w);
                float cr = __expf(m[r] - nm);
                corr[r] = cr;
                l[r] = l[r] * cr + sum;
                m[r] = nm;
            }
            int grp = half * 16 + trow;
            #pragma unroll
            for (int cc = 0; cc < 8; cc++) {
                int key = (cc < 4) ? (tcol * 4 + cc) : (64 + tcol * 4 + (cc - 4));
                int gp  = grp ^ ((key >> 2) & 7);
                float4 st = make_float4(pp[0][cc], pp[1][cc], pp[2][cc], pp[3][cc]);
                *(float4*)&Pts[key * 128 + gp * 4] = st;
            }
        }

        #pragma unroll
        for (int rp = 0; rp < 4; rp++) {
            ull cp = pack2(corr[2 * rp], corr[2 * rp + 1]);
            #pragma unroll
            for (int d = 0; d < 4; d++) fmul2(o2[rp][d], cp);
        }
        __syncthreads();

        #pragma unroll 4
        for (int k = 0; k < ATT_BC; k++) {
            int swk = (k >> 2) & 7;
            const float* prow = &Pts[k * 128];
            float4 plo = *(const float4*)(prow + ((trow ^ swk) << 2));
            float4 phi = *(const float4*)(prow + (((16 + trow) ^ swk) << 2));
            float4 vv4 = *(const float4*)&Vs[k * 64 + tcol * 4];
            ull pr[4];
            pr[0] = pack2(plo.x, plo.y);
            pr[1] = pack2(plo.z, plo.w);
            pr[2] = pack2(phi.x, phi.y);
            pr[3] = pack2(phi.z, phi.w);
            ull vv[4];
            vv[0] = splat2(vv4.x);
            vv[1] = splat2(vv4.y);
            vv[2] = splat2(vv4.z);
            vv[3] = splat2(vv4.w);
            #pragma unroll
            for (int rp = 0; rp < 4; rp++) {
                ffma2(o2[rp][0], pr[rp], vv[0]);
                ffma2(o2[rp][1], pr[rp], vv[1]);
                ffma2(o2[rp][2], pr[rp], vv[2]);
                ffma2(o2[rp][3], pr[rp], vv[3]);
            }
        }
    }

    #pragma unroll
    for (int r = 0; r < 8; r++) {
        float inv = 1.0f / l[r];
        int qrow = (r < 4) ? (trow * 4 + r) : (64 + trow * 4 + (r - 4));
        int rp = r >> 1;
        float e[4][2];
        unpack2(o2[rp][0], e[0][0], e[0][1]);
        unpack2(o2[rp][1], e[1][0], e[1][1]);
        unpack2(o2[rp][2], e[2][0], e[2][1]);
        unpack2(o2[rp][3], e[3][0], e[3][1]);
        int hi = r & 1;
        float4 out;
        out.x = e[0][hi] * inv;
        out.y = e[1][hi] * inv;
        out.z = e[2][hi] * inv;
        out.w = e[3][hi] * inv;
        *(float4*)(Og + headoff + (size_t)(q0 + qrow) * Dm + tcol * 4) = out;
    }
}

// ---------------------------------------------------------------------------
extern "C" void kernel_launch(void* const* d_in, const int* in_sizes, int n_in,
                              void* d_out, int out_size)
{
    const float* x  = (const float*)d_in[0];
    const float* wq = (const float*)d_in[1];
    const float* bq = (const float*)d_in[2];
    const float* wk = (const float*)d_in[3];
    const float* bk = (const float*)d_in[4];
    const float* wv = (const float*)d_in[5];
    const float* bv = (const float*)d_in[6];
    const float* wo = (const float*)d_in[7];
    const float* bo = (const float*)d_in[8];
    float* out = (float*)d_out;

    float *qp, *kp, *vp, *aop;
    __nv_bfloat16 *ahi, *alo, *wthi, *wtlo;
    cudaGetSymbolAddress((void**)&qp,   g_Q);
    cudaGetSymbolAddress((void**)&kp,   g_K);
    cudaGetSymbolAddress((void**)&vp,   g_V);
    cudaGetSymbolAddress((void**)&aop,  g_AO);
    cudaGetSymbolAddress((void**)&ahi,  g_Ahi);
    cudaGetSymbolAddress((void**)&alo,  g_Alo);
    cudaGetSymbolAddress((void**)&wthi, g_Wthi);
    cudaGetSymbolAddress((void**)&wtlo, g_Wtlo);

    cudaFuncSetAttribute(attn_flash2,
                         cudaFuncAttributeMaxDynamicSharedMemorySize, ATT_SMEM);
    cudaFuncSetAttribute(gemm_hmma,
                         cudaFuncAttributeMaxDynamicSharedMemorySize, HSMEM);

    const int n4 = MROWS * Dm / 4;
    dim3 gt(Dm / 32, Dm / 32);        // transpose grid
    dim3 gg(Dm / 128, MROWS / 128);   // (8, 64)

    // split x once; Q/K/V gemms reuse it
    fsplit<<<(n4 + 255) / 256, 256>>>((const float4*)x, (uint2*)ahi, (uint2*)alo, n4);

    wt_split<<<gt, 256>>>(wq, wthi, wtlo);
    gemm_hmma<<<gg, 256, HSMEM>>>(ahi, alo, wthi, wtlo, bq, qp);
    wt_split<<<gt, 256>>>(wk, wthi, wtlo);
    gemm_hmma<<<gg, 256, HSMEM>>>(ahi, alo, wthi, wtlo, bk, kp);
    wt_split<<<gt, 256>>>(wv, wthi, wtlo);
    gemm_hmma<<<gg, 256, HSMEM>>>(ahi, alo, wthi, wtlo, bv, vp);

    dim3 ga(Sq / ATT_BR, Bsz * Hn);   // (16, 64)
    attn_flash2<<<ga, 256, ATT_SMEM>>>(qp, kp, vp, aop);

    fsplit<<<(n4 + 255) / 256, 256>>>((const float4*)aop, (uint2*)ahi, (uint2*)alo, n4);
    wt_split<<<gt, 256>>>(wo, wthi, wtlo);
    gemm_hmma<<<gg, 256, HSMEM>>>(ahi, alo, wthi, wtlo, bo, out);
}

// round 5
// speedup vs baseline: 5.7235x; 2.0114x over previous
#include <cuda_runtime.h>
#include <cuda_bf16.h>
#include <math.h>
#include <float.h>
#include <stdint.h>

// Problem constants
#define Bsz 4
#define Sq  2048
#define Dm  1024
#define Hn  16
#define HD  64
#define MROWS (Bsz * Sq)          // 8192

typedef unsigned long long ull;
typedef __nv_bfloat16 bf16;

// ============================ PTX helpers ==================================
__device__ __forceinline__ uint32_t smem_u32(const void* p) {
    uint32_t a;
    asm("{ .reg .u64 t; cvta.to.shared.u64 t, %1; cvt.u32.u64 %0, t; }"
        : "=r"(a) : "l"(p));
    return a;
}
#define SWZ128(o) ((o) ^ (((o) >> 3) & 0x70))

__device__ __forceinline__ void cpa16(uint32_t saddr, const void* g) {
    asm volatile("cp.async.cg.shared.global [%0], [%1], 16;"
                 :: "r"(saddr), "l"(g) : "memory");
}
#define CP_COMMIT() asm volatile("cp.async.commit_group;" ::: "memory")
#define CP_WAIT1()  asm volatile("cp.async.wait_group 1;" ::: "memory")
#define CP_WAIT0()  asm volatile("cp.async.wait_group 0;" ::: "memory")

__device__ __forceinline__ void ldsm4(uint32_t* r, uint32_t addr) {
    asm volatile("ldmatrix.sync.aligned.m8n8.x4.shared.b16 {%0,%1,%2,%3}, [%4];"
                 : "=r"(r[0]), "=r"(r[1]), "=r"(r[2]), "=r"(r[3]) : "r"(addr));
}
__device__ __forceinline__ void ldsm4t(uint32_t* r, uint32_t addr) {
    asm volatile("ldmatrix.sync.aligned.m8n8.x4.trans.shared.b16 {%0,%1,%2,%3}, [%4];"
                 : "=r"(r[0]), "=r"(r[1]), "=r"(r[2]), "=r"(r[3]) : "r"(addr));
}
__device__ __forceinline__ void mma_bf16(float* d, const uint32_t* a, const uint32_t* b) {
    asm volatile(
        "mma.sync.aligned.m16n8k16.row.col.f32.bf16.bf16.f32 "
        "{%0,%1,%2,%3}, {%4,%5,%6,%7}, {%8,%9}, {%0,%1,%2,%3};"
        : "+f"(d[0]), "+f"(d[1]), "+f"(d[2]), "+f"(d[3])
        : "r"(a[0]), "r"(a[1]), "r"(a[2]), "r"(a[3]), "r"(b[0]), "r"(b[1]));
}
// pack two f32 -> bf16x2 register {lo, hi}
__device__ __forceinline__ uint32_t pk_bf16x2(float lo, float hi) {
    uint32_t r;
    asm("cvt.rn.bf16x2.f32 %0, %1, %2;" : "=r"(r) : "f"(hi), "f"(lo));
    return r;
}
__device__ __forceinline__ void upk_bf16x2(uint32_t v, float& lo, float& hi) {
    __nv_bfloat162 t = *reinterpret_cast<__nv_bfloat162*>(&v);
    lo = __bfloat162float(t.x); hi = __bfloat162float(t.y);
}

// ============================ scratch ======================================
__device__ bf16 g_Ahi[MROWS * Dm];
__device__ bf16 g_Alo[MROWS * Dm];
__device__ bf16 g_Wthi[Dm * Dm];
__device__ bf16 g_Wtlo[Dm * Dm];
__device__ bf16 g_Qh[MROWS * Dm];
__device__ bf16 g_Ql[MROWS * Dm];
__device__ bf16 g_Kh[MROWS * Dm];
__device__ bf16 g_Kl[MROWS * Dm];
__device__ bf16 g_Vh[MROWS * Dm];
__device__ bf16 g_Vl[MROWS * Dm];
__device__ bf16 g_Oh[MROWS * Dm];
__device__ bf16 g_Ol[MROWS * Dm];

// =================== split conversion: f32 -> bf16 hi/lo ===================
__device__ __forceinline__ void bsplit(float x, bf16 &h, bf16 &l) {
    h = __float2bfloat16(x);
    l = __float2bfloat16(x - __bfloat162float(h));
}

__global__ __launch_bounds__(256)
void fsplit(const float4* __restrict__ in, uint2* __restrict__ hi,
            uint2* __restrict__ lo, int n4)
{
    int i = blockIdx.x * 256 + threadIdx.x;
    if (i >= n4) return;
    float4 v = in[i];
    bf16 h0, h1, h2, h3, l0, l1, l2, l3;
    bsplit(v.x, h0, l0); bsplit(v.y, h1, l1);
    bsplit(v.z, h2, l2); bsplit(v.w, h3, l3);
    __nv_bfloat162 ph0 = __nv_bfloat162(h0, h1), ph1 = __nv_bfloat162(h2, h3);
    __nv_bfloat162 pl0 = __nv_bfloat162(l0, l1), pl1 = __nv_bfloat162(l2, l3);
    uint2 H, L;
    H.x = *(unsigned*)&ph0; H.y = *(unsigned*)&ph1;
    L.x = *(unsigned*)&pl0; L.y = *(unsigned*)&pl1;
    hi[i] = H; lo[i] = L;
}

// ========== transpose + split: W[K,N] f32 -> Wt[N,K] bf16 hi/lo ============
__global__ __launch_bounds__(256)
void wt_split(const float* __restrict__ W, bf16* __restrict__ Thi,
              bf16* __restrict__ Tlo)
{
    __shared__ float t[32][33];
    int n0 = blockIdx.x * 32, k0 = blockIdx.y * 32;
    int tx = threadIdx.x & 31, ty = threadIdx.x >> 5;   // 32 x 8
    #pragma unroll
    for (int i = 0; i < 4; i++)
        t[ty + 8 * i][tx] = W[(size_t)(k0 + ty + 8 * i) * Dm + n0 + tx];
    __syncthreads();
    #pragma unroll
    for (int i = 0; i < 4; i++) {
        float v = t[tx][ty + 8 * i];
        bf16 h, l; bsplit(v, h, l);
        size_t o = (size_t)(n0 + ty + 8 * i) * Dm + k0 + tx;
        Thi[o] = h; Tlo[o] = l;
    }
}

// ================== HMMA bf16-split GEMM + bias ===========================
// mode 0: write f32 to Cf.  mode 1: write bf16 hi/lo to Ch/Cl.
#define HBK 64
#define HBUF 65536
#define HSMEM (2 * HBUF)
#define HCHUNKS (Dm / HBK)

__global__ __launch_bounds__(256, 1)
void gemm_hmma(const bf16* __restrict__ Ahi, const bf16* __restrict__ Alo,
               const bf16* __restrict__ Bhi, const bf16* __restrict__ Blo,
               const float* __restrict__ bias,
               float* __restrict__ Cf, bf16* __restrict__ Ch,
               bf16* __restrict__ Cl, int mode)
{
    extern __shared__ __align__(1024) char smem[];
    const uint32_t sb = smem_u32(smem);

    const int tid  = threadIdx.x;
    const int wid  = tid >> 5;
    const int lane = tid & 31;
    const int wm   = wid & 3;
    const int wn   = wid >> 2;
    const int bm   = blockIdx.y * 128;
    const int bn   = blockIdx.x * 128;

    const int lrow = tid >> 3;
    const int lseg = tid & 7;

    float acc[2][8][4];
    #pragma unroll
    for (int fm = 0; fm < 2; fm++)
        #pragma unroll
        for (int fn = 0; fn < 8; fn++)
            #pragma unroll
            for (int e = 0; e < 4; e++) acc[fm][fn][e] = 0.0f;

    auto issue = [&](int c) {
        const uint32_t s0 = sb + (uint32_t)(c & 1) * HBUF;
        const size_t gofs = (size_t)c * HBK + lseg * 8;
        #pragma unroll
        for (int i = 0; i < 4; i++) {
            int row = lrow + i * 32;
            uint32_t so = SWZ128((uint32_t)(row * 128 + lseg * 16));
            cpa16(s0 + so,         Ahi + (size_t)(bm + row) * Dm + gofs);
            cpa16(s0 + 16384 + so, Alo + (size_t)(bm + row) * Dm + gofs);
            cpa16(s0 + 32768 + so, Bhi + (size_t)(bn + row) * Dm + gofs);
            cpa16(s0 + 49152 + so, Blo + (size_t)(bn + row) * Dm + gofs);
        }
    };

    const int a_row = wm * 32 + (lane & 15);
    const int a_sel = lane >> 4;
    const int b_row = wn * 64 + ((lane >> 4) << 3) + (lane & 7);
    const int b_sel = (lane >> 3) & 1;

    issue(0);
    CP_COMMIT();

    for (int c = 0; c < HCHUNKS; c++) {
        if (c + 1 < HCHUNKS) { issue(c + 1); CP_COMMIT(); CP_WAIT1(); }
        else { CP_COMMIT(); CP_WAIT0(); }
        __syncthreads();

        const uint32_t s0 = sb + (uint32_t)(c & 1) * HBUF;
        #pragma unroll
        for (int ks = 0; ks < 4; ks++) {
            uint32_t ah[2][4], al[2][4];
            #pragma unroll
            for (int fm = 0; fm < 2; fm++) {
                int row = a_row + fm * 16;
                int seg = 2 * ks + a_sel;
                uint32_t ad = s0 + SWZ128((uint32_t)(row * 128 + seg * 16));
                ldsm4(ah[fm], ad);
                ldsm4(al[fm], ad + 16384);
            }
            uint32_t bh[8][2], bl[8][2];
            #pragma unroll
            for (int f2 = 0; f2 < 4; f2++) {
                int row = b_row + f2 * 16;
                int seg = 2 * ks + b_sel;
                uint32_t bd = s0 + 32768 + SWZ128((uint32_t)(row * 128 + seg * 16));
                uint32_t t[4], u[4];
                ldsm4(t, bd);
                ldsm4(u, bd + 16384);
                bh[2*f2][0] = t[0]; bh[2*f2][1] = t[1];
                bh[2*f2+1][0] = t[2]; bh[2*f2+1][1] = t[3];
                bl[2*f2][0] = u[0]; bl[2*f2][1] = u[1];
                bl[2*f2+1][0] = u[2]; bl[2*f2+1][1] = u[3];
            }
            #pragma unroll
            for (int fm = 0; fm < 2; fm++)
                #pragma unroll
                for (int fn = 0; fn < 8; fn++) {
                    mma_bf16(acc[fm][fn], ah[fm], bh[fn]);
                    mma_bf16(acc[fm][fn], ah[fm], bl[fn]);
                    mma_bf16(acc[fm][fn], al[fm], bh[fn]);
                }
        }
        __syncthreads();
    }

    const int g  = lane >> 2;
    const int tq = lane & 3;
    #pragma unroll
    for (int fm = 0; fm < 2; fm++) {
        #pragma unroll
        for (int fn = 0; fn < 8; fn++) {
            int r0 = bm + wm * 32 + fm * 16 + g;
            int cc = bn + wn * 64 + fn * 8 + tq * 2;
            float b0 = bias[cc], b1 = bias[cc + 1];
            float v00 = acc[fm][fn][0] + b0, v01 = acc[fm][fn][1] + b1;
            float v10 = acc[fm][fn][2] + b0, v11 = acc[fm][fn][3] + b1;
            if (mode == 0) {
                *(float2*)(Cf + (size_t)r0 * Dm + cc) = make_float2(v00, v01);
                *(float2*)(Cf + (size_t)(r0 + 8) * Dm + cc) = make_float2(v10, v11);
            } else {
                bf16 h, l;
                uint32_t hp, lp; float hf0, hf1;
                // row r0
                hp = pk_bf16x2(v00, v01);
                upk_bf16x2(hp, hf0, hf1);
                lp = pk_bf16x2(v00 - hf0, v01 - hf1);
                *(uint32_t*)(Ch + (size_t)r0 * Dm + cc) = hp;
                *(uint32_t*)(Cl + (size_t)r0 * Dm + cc) = lp;
                // row r0+8
                hp = pk_bf16x2(v10, v11);
                upk_bf16x2(hp, hf0, hf1);
                lp = pk_bf16x2(v10 - hf0, v11 - hf1);
                *(uint32_t*)(Ch + (size_t)(r0 + 8) * Dm + cc) = hp;
                *(uint32_t*)(Cl + (size_t)(r0 + 8) * Dm + cc) = lp;
                (void)h; (void)l;
            }
        }
    }
}

// ---------------------------------------------------------------------------
// HMMA bf16-split flash attention.
// Br=128 (8 warps x m16), Bc=128, HD=64. 3-term split on both QK^T and PV.
// smem: Qh|Ql (32KB) + double-buffered Kh|Kl|Vh|Vl (2x64KB) = 160KB.
// ---------------------------------------------------------------------------
#define AQ_OFF  0
#define AKV_OFF 32768
#define AKVBUF  65536
#define ATT_SMEM (AKV_OFF + 2 * AKVBUF)   // 163840
#define C2EXP 0.18033688011112042f        // 0.125 * log2(e)

__global__ __launch_bounds__(256, 1)
void attn_hmma(const bf16* __restrict__ Qh, const bf16* __restrict__ Ql,
               const bf16* __restrict__ Kh, const bf16* __restrict__ Kl,
               const bf16* __restrict__ Vh, const bf16* __restrict__ Vl,
               bf16* __restrict__ Oh, bf16* __restrict__ Ol)
{
    extern __shared__ __align__(1024) char smem[];
    const uint32_t sb = smem_u32(smem);

    const int tid  = threadIdx.x;
    const int wid  = tid >> 5;
    const int lane = tid & 31;
    const int g    = lane >> 2;
    const int tq   = lane & 3;

    const int bh = blockIdx.y;
    const int b  = bh >> 4;
    const int h  = bh & 15;
    const int q0 = blockIdx.x * 128;
    const size_t headoff = (size_t)(b * Sq) * Dm + h * HD;

    // ---- async load helpers ----
    const int lr = tid >> 1;            // 0..127
    const int sh = (tid & 1) * 4;       // seg base

    auto issueQ = [&]() {
        size_t gro = headoff + (size_t)(q0 + lr) * Dm;
        #pragma unroll
        for (int u = 0; u < 4; u++) {
            int seg = sh + u;
            uint32_t so = SWZ128((uint32_t)(lr * 128 + seg * 16));
            cpa16(sb + AQ_OFF + so,         Qh + gro + seg * 8);
            cpa16(sb + AQ_OFF + 16384 + so, Ql + gro + seg * 8);
        }
    };
    auto issueKV = [&](int t) {
        const uint32_t s0 = sb + AKV_OFF + (uint32_t)(t & 1) * AKVBUF;
        size_t gro = headoff + (size_t)(t * 128 + lr) * Dm;
        #pragma unroll
        for (int u = 0; u < 4; u++) {
            int seg = sh + u;
            uint32_t so = SWZ128((uint32_t)(lr * 128 + seg * 16));
            cpa16(s0 + so,         Kh + gro + seg * 8);
            cpa16(s0 + 16384 + so, Kl + gro + seg * 8);
            cpa16(s0 + 32768 + so, Vh + gro + seg * 8);
            cpa16(s0 + 49152 + so, Vl + gro + seg * 8);
        }
    };

    issueQ();  CP_COMMIT();
    issueKV(0); CP_COMMIT();
    CP_WAIT1();           // Q group done
    __syncthreads();

    // ---- Q fragments, register resident: m16 x k64 (4 k-steps), hi/lo ----
    uint32_t qh[4][4], ql[4][4];
    {
        int arow = wid * 16 + (lane & 15);
        int asel = lane >> 4;
        #pragma unroll
        for (int ks = 0; ks < 4; ks++) {
            uint32_t ad = sb + AQ_OFF + SWZ128((uint32_t)(arow * 128 + (2 * ks + asel) * 16));
            ldsm4(qh[ks], ad);
            ldsm4(ql[ks], ad + 16384);
        }
    }

    float o[8][4];
    #pragma unroll
    for (int fn = 0; fn < 8; fn++)
        #pragma unroll
        for (int e = 0; e < 4; e++) o[fn][e] = 0.0f;
    float m0 = -1e30f, m1 = -1e30f, l0 = 0.0f, l1 = 0.0f;

    const int kb_row = ((lane >> 4) << 3) + (lane & 7);   // b-frag row within n16
    const int kb_sel = (lane >> 3) & 1;
    const int vt_row = ((lane >> 3) & 1) * 8 + (lane & 7); // trans row within k16
    const int vt_off = (lane >> 4) * 16;                   // +8 dims

    for (int t = 0; t < 16; t++) {
        __syncthreads();   // all done reading buffer (t+1)&1 from iter t-1
        if (t + 1 < 16) { issueKV(t + 1); CP_COMMIT(); CP_WAIT1(); }
        else { CP_WAIT0(); }
        __syncthreads();

        const uint32_t s0 = sb + AKV_OFF + (uint32_t)(t & 1) * AKVBUF;

        // ---- S = Q K^T : m16 x n128 x k64, 3-term split ----
        float s[16][4];
        #pragma unroll
        for (int fn = 0; fn < 16; fn++)
            #pragma unroll
            for (int e = 0; e < 4; e++) s[fn][e] = 0.0f;

        #pragma unroll
        for (int ks = 0; ks < 4; ks++) {
            #pragma unroll
            for (int ng = 0; ng < 8; ng++) {
                uint32_t kh[4], kl[4];
                uint32_t bd = s0 + SWZ128((uint32_t)((ng * 16 + kb_row) * 128 +
                                                     (2 * ks + kb_sel) * 16));
                ldsm4(kh, bd);
                ldsm4(kl, bd + 16384);
                mma_bf16(s[2*ng],   qh[ks], kh);
                mma_bf16(s[2*ng],   qh[ks], kl);
                mma_bf16(s[2*ng],   ql[ks], kh);
                mma_bf16(s[2*ng+1], qh[ks], kh + 2);
                mma_bf16(s[2*ng+1], qh[ks], kl + 2);
                mma_bf16(s[2*ng+1], ql[ks], kh + 2);
            }
        }

        // ---- online softmax (rows g and g+8, warp-local quad reduce) ----
        float mx0 = -1e30f, mx1 = -1e30f;
        #pragma unroll
        for (int fn = 0; fn < 16; fn++) {
            mx0 = fmaxf(mx0, fmaxf(s[fn][0], s[fn][1]));
            mx1 = fmaxf(mx1, fmaxf(s[fn][2], s[fn][3]));
        }
        mx0 = fmaxf(mx0, __shfl_xor_sync(0xffffffffu, mx0, 1));
        mx0 = fmaxf(mx0, __shfl_xor_sync(0xffffffffu, mx0, 2));
        mx1 = fmaxf(mx1, __shfl_xor_sync(0xffffffffu, mx1, 1));
        mx1 = fmaxf(mx1, __shfl_xor_sync(0xffffffffu, mx1, 2));
        float nm0 = fmaxf(m0, mx0);
        float nm1 = fmaxf(m1, mx1);

        float sum0 = 0.0f, sum1 = 0.0f;
        #pragma unroll
        for (int fn = 0; fn < 16; fn++) {
            s[fn][0] = exp2f((s[fn][0] - nm0) * C2EXP);
            s[fn][1] = exp2f((s[fn][1] - nm0) * C2EXP);
            s[fn][2] = exp2f((s[fn][2] - nm1) * C2EXP);
            s[fn][3] = exp2f((s[fn][3] - nm1) * C2EXP);
            sum0 += s[fn][0] + s[fn][1];
            sum1 += s[fn][2] + s[fn][3];
        }
        sum0 += __shfl_xor_sync(0xffffffffu, sum0, 1);
        sum0 += __shfl_xor_sync(0xffffffffu, sum0, 2);
        sum1 += __shfl_xor_sync(0xffffffffu, sum1, 1);
        sum1 += __shfl_xor_sync(0xffffffffu, sum1, 2);

        float c0 = exp2f((m0 - nm0) * C2EXP);
        float c1 = exp2f((m1 - nm1) * C2EXP);
        l0 = l0 * c0 + sum0;  m0 = nm0;
        l1 = l1 * c1 + sum1;  m1 = nm1;
        #pragma unroll
        for (int fn = 0; fn < 8; fn++) {
            o[fn][0] *= c0; o[fn][1] *= c0;
            o[fn][2] *= c1; o[fn][3] *= c1;
        }

        // ---- O += P V : per 16-key chunk; split P hi/lo on the fly ----
        #pragma unroll
        for (int kc = 0; kc < 8; kc++) {
            uint32_t ph[4], pl[4];
            #pragma unroll
            for (int q = 0; q < 4; q++) {
                const float* sv = s[2 * kc + (q >> 1)];
                float p0 = sv[(q & 1) * 2], p1 = sv[(q & 1) * 2 + 1];
                uint32_t hp = pk_bf16x2(p0, p1);
                float h0, h1; upk_bf16x2(hp, h0, h1);
                ph[q] = hp;
                pl[q] = pk_bf16x2(p0 - h0, p1 - h1);
            }
            // a-frag order must be: a0=(rowg,klo) a1=(rowg+8,klo) a2=(rowg,khi) a3=(rowg+8,khi)
            uint32_t ah[4] = {ph[0], ph[1], ph[2], ph[3]};
            uint32_t al[4] = {pl[0], pl[1], pl[2], pl[3]};
            #pragma unroll
            for (int dh = 0; dh < 2; dh++) {      // d0 = 0,16 then 32,48
                #pragma unroll
                for (int dd = 0; dd < 2; dd++) {
                    int d0 = (dh * 2 + dd) * 16;
                    uint32_t vd = s0 + 32768 +
                        SWZ128((uint32_t)((kc * 16 + vt_row) * 128 + d0 * 2 + vt_off));
                    uint32_t vh[4], vl[4];
                    ldsm4t(vh, vd);
                    ldsm4t(vl, vd + 16384);
                    int f0 = d0 >> 3;
                    mma_bf16(o[f0],     ah, vh);
                    mma_bf16(o[f0],     ah, vl);
                    mma_bf16(o[f0],     al, vh);
                    mma_bf16(o[f0 + 1], ah, vh + 2);
                    mma_bf16(o[f0 + 1], ah, vl + 2);
                    mma_bf16(o[f0 + 1], al, vh + 2);
                }
            }
        }
    }

    // ---- normalize + store bf16 hi/lo ----
    float inv0 = 1.0f / l0, inv1 = 1.0f / l1;
    int r0 = q0 + wid * 16 + g;
    #pragma unroll
    for (int fn = 0; fn < 8; fn++) {
        int cc = fn * 8 + tq * 2;
        float v00 = o[fn][0] * inv0, v01 = o[fn][1] * inv0;
        float v10 = o[fn][2] * inv1, v11 = o[fn][3] * inv1;
        uint32_t hp, lp; float h0, h1;
        hp = pk_bf16x2(v00, v01);
        upk_bf16x2(hp, h0, h1);
        lp = pk_bf16x2(v00 - h0, v01 - h1);
        *(uint32_t*)(Oh + headoff + (size_t)r0 * Dm + cc) = hp;
        *(uint32_t*)(Ol + headoff + (size_t)r0 * Dm + cc) = lp;
        hp = pk_bf16x2(v10, v11);
        upk_bf16x2(hp, h0, h1);
        lp = pk_bf16x2(v10 - h0, v11 - h1);
        *(uint32_t*)(Oh + headoff + (size_t)(r0 + 8) * Dm + cc) = hp;
        *(uint32_t*)(Ol + headoff + (size_t)(r0 + 8) * Dm + cc) = lp;
    }
}

// ---------------------------------------------------------------------------
extern "C" void kernel_launch(void* const* d_in, const int* in_sizes, int n_in,
                              void* d_out, int out_size)
{
    const float* x  = (const float*)d_in[0];
    const float* wq = (const float*)d_in[1];
    const float* bq = (const float*)d_in[2];
    const float* wk = (const float*)d_in[3];
    const float* bk = (const float*)d_in[4];
    const float* wv = (const float*)d_in[5];
    const float* bv = (const float*)d_in[6];
    const float* wo = (const float*)d_in[7];
    const float* bo = (const float*)d_in[8];
    float* out = (float*)d_out;

    bf16 *ahi, *alo, *wthi, *wtlo;
    bf16 *qh, *ql, *kh, *kl, *vh, *vl, *oh, *ol;
    cudaGetSymbolAddress((void**)&ahi,  g_Ahi);
    cudaGetSymbolAddress((void**)&alo,  g_Alo);
    cudaGetSymbolAddress((void**)&wthi, g_Wthi);
    cudaGetSymbolAddress((void**)&wtlo, g_Wtlo);
    cudaGetSymbolAddress((void**)&qh,   g_Qh);
    cudaGetSymbolAddress((void**)&ql,   g_Ql);
    cudaGetSymbolAddress((void**)&kh,   g_Kh);
    cudaGetSymbolAddress((void**)&kl,   g_Kl);
    cudaGetSymbolAddress((void**)&vh,   g_Vh);
    cudaGetSymbolAddress((void**)&vl,   g_Vl);
    cudaGetSymbolAddress((void**)&oh,   g_Oh);
    cudaGetSymbolAddress((void**)&ol,   g_Ol);

    cudaFuncSetAttribute(gemm_hmma,
                         cudaFuncAttributeMaxDynamicSharedMemorySize, HSMEM);
    cudaFuncSetAttribute(attn_hmma,
                         cudaFuncAttributeMaxDynamicSharedMemorySize, ATT_SMEM);

    const int n4 = MROWS * Dm / 4;
    dim3 gt(Dm / 32, Dm / 32);
    dim3 gg(Dm / 128, MROWS / 128);   // (8, 64)

    fsplit<<<(n4 + 255) / 256, 256>>>((const float4*)x, (uint2*)ahi, (uint2*)alo, n4);

    wt_split<<<gt, 256>>>(wq, wthi, wtlo);
    gemm_hmma<<<gg, 256, HSMEM>>>(ahi, alo, wthi, wtlo, bq, nullptr, qh, ql, 1);
    wt_split<<<gt, 256>>>(wk, wthi, wtlo);
    gemm_hmma<<<gg, 256, HSMEM>>>(ahi, alo, wthi, wtlo, bk, nullptr, kh, kl, 1);
    wt_split<<<gt, 256>>>(wv, wthi, wtlo);
    gemm_hmma<<<gg, 256, HSMEM>>>(ahi, alo, wthi, wtlo, bv, nullptr, vh, vl, 1);

    dim3 ga(Sq / 128, Bsz * Hn);      // (16, 64)
    attn_hmma<<<ga, 256, ATT_SMEM>>>(qh, ql, kh, kl, vh, vl, oh, ol);

    wt_split<<<gt, 256>>>(wo, wthi, wtlo);
    gemm_hmma<<<gg, 256, HSMEM>>>(oh, ol, wthi, wtlo, bo, out, nullptr, nullptr, 0);
}